// round 1
// baseline (speedup 1.0000x reference)
#include <cuda_runtime.h>
#include <math.h>

// Problem sizes
#define Bz 32
#define Sz 512
#define Iz 128
#define Hz 1024
#define Oz 128
#define TPB 256
#define SCAN_GRID 128

// Scratch (device globals: sanctioned alternative to cudaMalloc)
// layouts: gates [gate][t][j][b], seq [t][j][b], h/u [j][b]  (b innermost = coalesced)
__device__ float g_gates[(size_t)3 * Sz * Hz * Bz];   // ~201 MB
__device__ float g_seq[(size_t)Sz * Hz * Bz];         // ~67 MB
__device__ float g_h[Hz * Bz];
__device__ float g_u[Hz * Bz];
__device__ int   g_bar[2 * Sz];

__device__ __forceinline__ float sigmoidf_(float x) {
    return 1.0f / (1.0f + expf(-x));
}

// Software grid barrier: one fresh counter per barrier instance (no reuse -> no reset race).
__device__ __forceinline__ void grid_bar(int* c, int target) {
    __syncthreads();
    if (threadIdx.x == 0) {
        __threadfence();                 // release: publish our phase's writes
        atomicAdd(c, 1);
        while (*(volatile int*)c < target) { }
        __threadfence();                 // acquire: see everyone else's writes
    }
    __syncthreads();
}

// ---------------------------------------------------------------------------
// prep: h state init (transposed) + zero the barrier counters
// grid 128 x 256  (idx covers Hz*Bz = 32768)
// ---------------------------------------------------------------------------
__global__ void prep_kernel(const float* __restrict__ h0, int layer) {
    int idx = blockIdx.x * TPB + threadIdx.x;
    int j = idx >> 5;
    int b = idx & 31;
    g_h[idx] = h0[b * (2 * Hz) + layer * Hz + j];   // h0: [B][L][H]
    if (idx < 2 * Sz) g_bar[idx] = 0;
}

// ---------------------------------------------------------------------------
// proj0: layer-0 input projections. gates[g][s][j][b] = sum_i x[b][s][i] * W_g[j][i]
// grid = 512 (one CTA per s), 256 threads. K = 128 fits one smem tile.
// ---------------------------------------------------------------------------
__global__ void __launch_bounds__(TPB) proj0_kernel(
    const float* __restrict__ x,
    const float* __restrict__ Wz, const float* __restrict__ Wr, const float* __restrict__ Wg)
{
    __shared__ float xs[Iz * 33];   // transposed tile [i][b], padded
    const int s = blockIdx.x;
    const int tid = threadIdx.x, lane = tid & 31, w = tid >> 5;

    #pragma unroll
    for (int rep = 0; rep < 16; ++rep) {
        int e = rep * 256 + tid;
        int b = e >> 7, i = e & 127;
        xs[i * 33 + b] = x[((size_t)b * Sz + s) * Iz + i];
    }
    __syncthreads();

    for (int c = 0; c < 96; ++c) {              // 96 chunks of 4 rows per warp
        int rr = w * 384 + c * 4;               // row in [0,3072): gate-major
        int g = rr >> 10;
        int j = rr & 1023;
        const float* Wp = (g == 0) ? Wz : ((g == 1) ? Wr : Wg);
        const float4* w0 = (const float4*)(Wp + (size_t)(j + 0) * Iz);
        const float4* w1 = (const float4*)(Wp + (size_t)(j + 1) * Iz);
        const float4* w2 = (const float4*)(Wp + (size_t)(j + 2) * Iz);
        const float4* w3 = (const float4*)(Wp + (size_t)(j + 3) * Iz);
        float a0 = 0.f, a1 = 0.f, a2 = 0.f, a3 = 0.f;
        #pragma unroll 8
        for (int i4 = 0; i4 < 32; ++i4) {
            float h0v = xs[(i4 * 4 + 0) * 33 + lane];
            float h1v = xs[(i4 * 4 + 1) * 33 + lane];
            float h2v = xs[(i4 * 4 + 2) * 33 + lane];
            float h3v = xs[(i4 * 4 + 3) * 33 + lane];
            float4 q0 = w0[i4], q1 = w1[i4], q2 = w2[i4], q3 = w3[i4];
            a0 = fmaf(q0.x, h0v, a0); a0 = fmaf(q0.y, h1v, a0); a0 = fmaf(q0.z, h2v, a0); a0 = fmaf(q0.w, h3v, a0);
            a1 = fmaf(q1.x, h0v, a1); a1 = fmaf(q1.y, h1v, a1); a1 = fmaf(q1.z, h2v, a1); a1 = fmaf(q1.w, h3v, a1);
            a2 = fmaf(q2.x, h0v, a2); a2 = fmaf(q2.y, h1v, a2); a2 = fmaf(q2.z, h2v, a2); a2 = fmaf(q2.w, h3v, a2);
            a3 = fmaf(q3.x, h0v, a3); a3 = fmaf(q3.y, h1v, a3); a3 = fmaf(q3.z, h2v, a3); a3 = fmaf(q3.w, h3v, a3);
        }
        size_t base = (((size_t)g * Sz + s) * Hz + j) * Bz + lane;
        g_gates[base +  0] = a0;
        g_gates[base + 32] = a1;
        g_gates[base + 64] = a2;
        g_gates[base + 96] = a3;
    }
}

// ---------------------------------------------------------------------------
// proj1: layer-1 input projections from g_seq (already [s][k][b]). K = 1024.
// grid = (8 rowblocks, 512 s), 256 threads. 48 persistent accumulators/thread.
// ---------------------------------------------------------------------------
__global__ void __launch_bounds__(TPB) proj1_kernel(
    const float* __restrict__ Wz, const float* __restrict__ Wr, const float* __restrict__ Wg)
{
    __shared__ float xs[256 * 33];  // [i][b] tile of seq, K-tile = 256
    const int s = blockIdx.y;
    const int rb = blockIdx.x;      // 0..7
    const int tid = threadIdx.x, lane = tid & 31, w = tid >> 5;

    float acc[48];
    #pragma unroll
    for (int q = 0; q < 48; ++q) acc[q] = 0.f;

    for (int kt = 0; kt < 4; ++kt) {
        __syncthreads();
        #pragma unroll
        for (int rep = 0; rep < 32; ++rep) {
            int e = rep * 256 + tid;
            int i = e >> 5, b = e & 31;
            xs[i * 33 + b] = g_seq[((size_t)s * Hz + kt * 256 + i) * Bz + b];
        }
        __syncthreads();
        #pragma unroll
        for (int c = 0; c < 12; ++c) {
            int rr = rb * 384 + w * 48 + c * 4;
            int g = rr >> 10, j = rr & 1023;
            const float* Wp = (g == 0) ? Wz : ((g == 1) ? Wr : Wg);
            const float4* w0 = (const float4*)(Wp + (size_t)(j + 0) * Hz + kt * 256);
            const float4* w1 = (const float4*)(Wp + (size_t)(j + 1) * Hz + kt * 256);
            const float4* w2 = (const float4*)(Wp + (size_t)(j + 2) * Hz + kt * 256);
            const float4* w3 = (const float4*)(Wp + (size_t)(j + 3) * Hz + kt * 256);
            float a0 = acc[c * 4 + 0], a1 = acc[c * 4 + 1];
            float a2 = acc[c * 4 + 2], a3 = acc[c * 4 + 3];
            #pragma unroll 8
            for (int i4 = 0; i4 < 64; ++i4) {
                float h0v = xs[(i4 * 4 + 0) * 33 + lane];
                float h1v = xs[(i4 * 4 + 1) * 33 + lane];
                float h2v = xs[(i4 * 4 + 2) * 33 + lane];
                float h3v = xs[(i4 * 4 + 3) * 33 + lane];
                float4 q0 = w0[i4], q1 = w1[i4], q2 = w2[i4], q3 = w3[i4];
                a0 = fmaf(q0.x, h0v, a0); a0 = fmaf(q0.y, h1v, a0); a0 = fmaf(q0.z, h2v, a0); a0 = fmaf(q0.w, h3v, a0);
                a1 = fmaf(q1.x, h0v, a1); a1 = fmaf(q1.y, h1v, a1); a1 = fmaf(q1.z, h2v, a1); a1 = fmaf(q1.w, h3v, a1);
                a2 = fmaf(q2.x, h0v, a2); a2 = fmaf(q2.y, h1v, a2); a2 = fmaf(q2.z, h2v, a2); a2 = fmaf(q2.w, h3v, a2);
                a3 = fmaf(q3.x, h0v, a3); a3 = fmaf(q3.y, h1v, a3); a3 = fmaf(q3.z, h2v, a3); a3 = fmaf(q3.w, h3v, a3);
            }
            acc[c * 4 + 0] = a0; acc[c * 4 + 1] = a1;
            acc[c * 4 + 2] = a2; acc[c * 4 + 3] = a3;
        }
    }
    #pragma unroll
    for (int c = 0; c < 12; ++c) {
        int rr = rb * 384 + w * 48 + c * 4;
        int g = rr >> 10, j = rr & 1023;
        size_t base = (((size_t)g * Sz + s) * Hz + j) * Bz + lane;
        g_gates[base +  0] = acc[c * 4 + 0];
        g_gates[base + 32] = acc[c * 4 + 1];
        g_gates[base + 64] = acc[c * 4 + 2];
        g_gates[base + 96] = acc[c * 4 + 3];
    }
}

// ---------------------------------------------------------------------------
// scan: persistent per-layer GRU recurrence. grid = 128 CTAs (1/SM, co-resident),
// 256 threads. Warp w owns column j = cta*8 + w for all gates; lane = batch b.
// ---------------------------------------------------------------------------
__global__ void __launch_bounds__(TPB) scan_kernel(
    const float* __restrict__ Whz, const float* __restrict__ Whr, const float* __restrict__ Whg,
    const float* __restrict__ bz,  const float* __restrict__ br,  const float* __restrict__ bg,
    float* __restrict__ hid_out, int layer)
{
    __shared__ float sh[128 * 33];  // [k][b] tile of h (or u)
    const int tid = threadIdx.x, lane = tid & 31, w = tid >> 5;
    const int j = blockIdx.x * 8 + w;
    const float* wzr = Whz + (size_t)j * Hz;
    const float* wrr = Whr + (size_t)j * Hz;
    const float* wgr = Whg + (size_t)j * Hz;
    const float bzj = bz[j], brj = br[j], bgj = bg[j];
    const int target = (int)gridDim.x;

    for (int t = 0; t < Sz; ++t) {
        // ---- phase 1: z, r, u = r*h -------------------------------------
        float accz = 0.f, accr = 0.f;
        for (int kt = 0; kt < 8; ++kt) {
            __syncthreads();
            #pragma unroll
            for (int rep = 0; rep < 16; ++rep) {
                int e = rep * 256 + tid;
                int i = e >> 5, b = e & 31;
                sh[i * 33 + b] = g_h[(kt * 128 + i) * 32 + b];
            }
            __syncthreads();
            const float4* z4 = (const float4*)(wzr + kt * 128);
            const float4* r4 = (const float4*)(wrr + kt * 128);
            #pragma unroll 8
            for (int i4 = 0; i4 < 32; ++i4) {
                float h0v = sh[(i4 * 4 + 0) * 33 + lane];
                float h1v = sh[(i4 * 4 + 1) * 33 + lane];
                float h2v = sh[(i4 * 4 + 2) * 33 + lane];
                float h3v = sh[(i4 * 4 + 3) * 33 + lane];
                float4 qz = z4[i4], qr = r4[i4];
                accz = fmaf(qz.x, h0v, accz); accr = fmaf(qr.x, h0v, accr);
                accz = fmaf(qz.y, h1v, accz); accr = fmaf(qr.y, h1v, accr);
                accz = fmaf(qz.z, h2v, accz); accr = fmaf(qr.z, h2v, accr);
                accz = fmaf(qz.w, h3v, accz); accr = fmaf(qr.w, h3v, accr);
            }
        }
        const size_t gbase = ((size_t)t * Hz + j) * Bz + lane;
        const size_t plane = (size_t)Sz * Hz * Bz;
        float zg = sigmoidf_(accz + g_gates[gbase] + bzj);
        float rg = sigmoidf_(accr + g_gates[plane + gbase] + brj);
        float hv = g_h[j * 32 + lane];
        g_u[j * 32 + lane] = rg * hv;

        grid_bar(&g_bar[2 * t], target);

        // ---- phase 2: g, h_new ------------------------------------------
        float accg = 0.f;
        for (int kt = 0; kt < 8; ++kt) {
            __syncthreads();
            #pragma unroll
            for (int rep = 0; rep < 16; ++rep) {
                int e = rep * 256 + tid;
                int i = e >> 5, b = e & 31;
                sh[i * 33 + b] = g_u[(kt * 128 + i) * 32 + b];
            }
            __syncthreads();
            const float4* g4 = (const float4*)(wgr + kt * 128);
            #pragma unroll 8
            for (int i4 = 0; i4 < 32; ++i4) {
                float h0v = sh[(i4 * 4 + 0) * 33 + lane];
                float h1v = sh[(i4 * 4 + 1) * 33 + lane];
                float h2v = sh[(i4 * 4 + 2) * 33 + lane];
                float h3v = sh[(i4 * 4 + 3) * 33 + lane];
                float4 qg = g4[i4];
                accg = fmaf(qg.x, h0v, accg);
                accg = fmaf(qg.y, h1v, accg);
                accg = fmaf(qg.z, h2v, accg);
                accg = fmaf(qg.w, h3v, accg);
            }
        }
        float gv = tanhf(accg + g_gates[2 * plane + gbase] + bgj);
        float hn = zg * hv + (1.0f - zg) * gv;
        g_h[j * 32 + lane] = hn;
        g_seq[gbase] = hn;
        if (t == Sz - 1) hid_out[lane * (2 * Hz) + layer * Hz + j] = hn;

        grid_bar(&g_bar[2 * t + 1], target);
    }
}

// ---------------------------------------------------------------------------
// projY: y[b][s][o] = sum_h seq[s][h][b] * Wy[o][h] + by[o]
// grid = 512 (per s), 256 threads, 16 accumulators/thread.
// ---------------------------------------------------------------------------
__global__ void __launch_bounds__(TPB) projy_kernel(
    const float* __restrict__ Wy, const float* __restrict__ by, float* __restrict__ y)
{
    __shared__ float xs[256 * 33];
    const int s = blockIdx.x;
    const int tid = threadIdx.x, lane = tid & 31, w = tid >> 5;

    float acc[16];
    #pragma unroll
    for (int q = 0; q < 16; ++q) acc[q] = 0.f;

    for (int kt = 0; kt < 4; ++kt) {
        __syncthreads();
        #pragma unroll
        for (int rep = 0; rep < 32; ++rep) {
            int e = rep * 256 + tid;
            int i = e >> 5, b = e & 31;
            xs[i * 33 + b] = g_seq[((size_t)s * Hz + kt * 256 + i) * Bz + b];
        }
        __syncthreads();
        #pragma unroll
        for (int c = 0; c < 4; ++c) {
            int o = w * 16 + c * 4;
            const float4* w0 = (const float4*)(Wy + (size_t)(o + 0) * Hz + kt * 256);
            const float4* w1 = (const float4*)(Wy + (size_t)(o + 1) * Hz + kt * 256);
            const float4* w2 = (const float4*)(Wy + (size_t)(o + 2) * Hz + kt * 256);
            const float4* w3 = (const float4*)(Wy + (size_t)(o + 3) * Hz + kt * 256);
            float a0 = acc[c * 4 + 0], a1 = acc[c * 4 + 1];
            float a2 = acc[c * 4 + 2], a3 = acc[c * 4 + 3];
            #pragma unroll 8
            for (int i4 = 0; i4 < 64; ++i4) {
                float h0v = xs[(i4 * 4 + 0) * 33 + lane];
                float h1v = xs[(i4 * 4 + 1) * 33 + lane];
                float h2v = xs[(i4 * 4 + 2) * 33 + lane];
                float h3v = xs[(i4 * 4 + 3) * 33 + lane];
                float4 q0 = w0[i4], q1 = w1[i4], q2 = w2[i4], q3 = w3[i4];
                a0 = fmaf(q0.x, h0v, a0); a0 = fmaf(q0.y, h1v, a0); a0 = fmaf(q0.z, h2v, a0); a0 = fmaf(q0.w, h3v, a0);
                a1 = fmaf(q1.x, h0v, a1); a1 = fmaf(q1.y, h1v, a1); a1 = fmaf(q1.z, h2v, a1); a1 = fmaf(q1.w, h3v, a1);
                a2 = fmaf(q2.x, h0v, a2); a2 = fmaf(q2.y, h1v, a2); a2 = fmaf(q2.z, h2v, a2); a2 = fmaf(q2.w, h3v, a2);
                a3 = fmaf(q3.x, h0v, a3); a3 = fmaf(q3.y, h1v, a3); a3 = fmaf(q3.z, h2v, a3); a3 = fmaf(q3.w, h3v, a3);
            }
            acc[c * 4 + 0] = a0; acc[c * 4 + 1] = a1;
            acc[c * 4 + 2] = a2; acc[c * 4 + 3] = a3;
        }
    }
    #pragma unroll
    for (int c = 0; c < 4; ++c) {
        #pragma unroll
        for (int q = 0; q < 4; ++q) {
            int o = w * 16 + c * 4 + q;
            y[(size_t)lane * (Sz * Oz) + (size_t)s * Oz + o] = acc[c * 4 + q] + by[o];
        }
    }
}

// ---------------------------------------------------------------------------
extern "C" void kernel_launch(void* const* d_in, const int* in_sizes, int n_in,
                              void* d_out, int out_size) {
    (void)in_sizes; (void)n_in; (void)out_size;
    const float* x    = (const float*)d_in[0];
    const float* h0   = (const float*)d_in[1];
    const float* Wxz0 = (const float*)d_in[2];
    const float* Whz0 = (const float*)d_in[3];
    const float* bz0  = (const float*)d_in[4];
    const float* Wxr0 = (const float*)d_in[5];
    const float* Whr0 = (const float*)d_in[6];
    const float* br0  = (const float*)d_in[7];
    const float* Wxg0 = (const float*)d_in[8];
    const float* Whg0 = (const float*)d_in[9];
    const float* bg0  = (const float*)d_in[10];
    const float* Wxz1 = (const float*)d_in[11];
    const float* Whz1 = (const float*)d_in[12];
    const float* bz1  = (const float*)d_in[13];
    const float* Wxr1 = (const float*)d_in[14];
    const float* Whr1 = (const float*)d_in[15];
    const float* br1  = (const float*)d_in[16];
    const float* Wxg1 = (const float*)d_in[17];
    const float* Whg1 = (const float*)d_in[18];
    const float* bg1  = (const float*)d_in[19];
    const float* Wy   = (const float*)d_in[20];
    const float* by   = (const float*)d_in[21];

    float* y   = (float*)d_out;                              // [B][S][O]
    float* hid = (float*)d_out + (size_t)Bz * Sz * Oz;       // [B][L][H]

    // Layer 0
    proj0_kernel<<<Sz, TPB>>>(x, Wxz0, Wxr0, Wxg0);
    prep_kernel<<<SCAN_GRID, TPB>>>(h0, 0);
    scan_kernel<<<SCAN_GRID, TPB>>>(Whz0, Whr0, Whg0, bz0, br0, bg0, hid, 0);

    // Layer 1
    proj1_kernel<<<dim3(8, Sz), TPB>>>(Wxz1, Wxr1, Wxg1);
    prep_kernel<<<SCAN_GRID, TPB>>>(h0, 1);
    scan_kernel<<<SCAN_GRID, TPB>>>(Whz1, Whr1, Whg1, bz1, br1, bg1, hid, 1);

    // Output head
    projy_kernel<<<Sz, TPB>>>(Wy, by, y);
}

// round 2
// speedup vs baseline: 2.2561x; 2.2561x over previous
#include <cuda_runtime.h>
#include <math.h>

// Problem sizes
#define Bz 32
#define Sz 512
#define Iz 128
#define Hz 1024
#define Oz 128
#define TPB 256
#define SCAN_GRID 128

// Scratch (device globals)
__device__ float g_gates[(size_t)3 * Sz * Hz * Bz];   // [gate][t][j][b]
__device__ float g_seq[(size_t)Sz * Hz * Bz];         // [t][j][b]
__device__ float g_h[Hz * Bz];                        // [j][b]
__device__ float g_u[Hz * Bz];                        // [j][b]
__device__ int   g_bar[2 * Sz];
__device__ int   g_flag[2 * Sz];

__device__ __forceinline__ float sigmoidf_(float x) {
    return 1.0f / (1.0f + expf(-x));
}

// Grid barrier: fresh counter+flag per instance. Arrivers release via fence ->
// atomicAdd; last arriver sets a SEPARATE single-writer flag; spinners poll it
// read-only (no line ping-pong).
__device__ __forceinline__ void grid_bar(int i, int ncta) {
    __syncthreads();
    if (threadIdx.x == 0) {
        __threadfence();
        int v = atomicAdd(&g_bar[i], 1);
        if (v == ncta - 1) {
            atomicExch(&g_flag[i], 1);
        } else {
            while (*(volatile int*)&g_flag[i] == 0) { }
        }
        __threadfence();
    }
    __syncthreads();
}

// ---------------------------------------------------------------------------
// prep: init h state (transposed) + zero barrier counters/flags
// ---------------------------------------------------------------------------
__global__ void prep_kernel(const float* __restrict__ h0, int layer) {
    int idx = blockIdx.x * TPB + threadIdx.x;
    int j = idx >> 5;
    int b = idx & 31;
    g_h[idx] = h0[b * (2 * Hz) + layer * Hz + j];
    if (idx < 2 * Sz) { g_bar[idx] = 0; g_flag[idx] = 0; }
}

// ---------------------------------------------------------------------------
// proj0: layer-0 input projections (K=128)
// ---------------------------------------------------------------------------
__global__ void __launch_bounds__(TPB) proj0_kernel(
    const float* __restrict__ x,
    const float* __restrict__ Wz, const float* __restrict__ Wr, const float* __restrict__ Wg)
{
    __shared__ float xs[Iz * 33];
    const int s = blockIdx.x;
    const int tid = threadIdx.x, lane = tid & 31, w = tid >> 5;

    #pragma unroll
    for (int rep = 0; rep < 16; ++rep) {
        int e = rep * 256 + tid;
        int b = e >> 7, i = e & 127;
        xs[i * 33 + b] = x[((size_t)b * Sz + s) * Iz + i];
    }
    __syncthreads();

    for (int c = 0; c < 96; ++c) {
        int rr = w * 384 + c * 4;
        int g = rr >> 10;
        int j = rr & 1023;
        const float* Wp = (g == 0) ? Wz : ((g == 1) ? Wr : Wg);
        const float4* w0 = (const float4*)(Wp + (size_t)(j + 0) * Iz);
        const float4* w1 = (const float4*)(Wp + (size_t)(j + 1) * Iz);
        const float4* w2 = (const float4*)(Wp + (size_t)(j + 2) * Iz);
        const float4* w3 = (const float4*)(Wp + (size_t)(j + 3) * Iz);
        float a0 = 0.f, a1 = 0.f, a2 = 0.f, a3 = 0.f;
        #pragma unroll 8
        for (int i4 = 0; i4 < 32; ++i4) {
            float h0v = xs[(i4 * 4 + 0) * 33 + lane];
            float h1v = xs[(i4 * 4 + 1) * 33 + lane];
            float h2v = xs[(i4 * 4 + 2) * 33 + lane];
            float h3v = xs[(i4 * 4 + 3) * 33 + lane];
            float4 q0 = w0[i4], q1 = w1[i4], q2 = w2[i4], q3 = w3[i4];
            a0 = fmaf(q0.x, h0v, a0); a0 = fmaf(q0.y, h1v, a0); a0 = fmaf(q0.z, h2v, a0); a0 = fmaf(q0.w, h3v, a0);
            a1 = fmaf(q1.x, h0v, a1); a1 = fmaf(q1.y, h1v, a1); a1 = fmaf(q1.z, h2v, a1); a1 = fmaf(q1.w, h3v, a1);
            a2 = fmaf(q2.x, h0v, a2); a2 = fmaf(q2.y, h1v, a2); a2 = fmaf(q2.z, h2v, a2); a2 = fmaf(q2.w, h3v, a2);
            a3 = fmaf(q3.x, h0v, a3); a3 = fmaf(q3.y, h1v, a3); a3 = fmaf(q3.z, h2v, a3); a3 = fmaf(q3.w, h3v, a3);
        }
        size_t base = (((size_t)g * Sz + s) * Hz + j) * Bz + lane;
        g_gates[base +  0] = a0;
        g_gates[base + 32] = a1;
        g_gates[base + 64] = a2;
        g_gates[base + 96] = a3;
    }
}

// ---------------------------------------------------------------------------
// proj1: layer-1 input projections (K=1024) from g_seq
// ---------------------------------------------------------------------------
__global__ void __launch_bounds__(TPB) proj1_kernel(
    const float* __restrict__ Wz, const float* __restrict__ Wr, const float* __restrict__ Wg)
{
    __shared__ float xs[256 * 33];
    const int s = blockIdx.y;
    const int rb = blockIdx.x;
    const int tid = threadIdx.x, lane = tid & 31, w = tid >> 5;

    float acc[48];
    #pragma unroll
    for (int q = 0; q < 48; ++q) acc[q] = 0.f;

    for (int kt = 0; kt < 4; ++kt) {
        __syncthreads();
        #pragma unroll
        for (int rep = 0; rep < 32; ++rep) {
            int e = rep * 256 + tid;
            int i = e >> 5, b = e & 31;
            xs[i * 33 + b] = g_seq[((size_t)s * Hz + kt * 256 + i) * Bz + b];
        }
        __syncthreads();
        #pragma unroll
        for (int c = 0; c < 12; ++c) {
            int rr = rb * 384 + w * 48 + c * 4;
            int g = rr >> 10, j = rr & 1023;
            const float* Wp = (g == 0) ? Wz : ((g == 1) ? Wr : Wg);
            const float4* w0 = (const float4*)(Wp + (size_t)(j + 0) * Hz + kt * 256);
            const float4* w1 = (const float4*)(Wp + (size_t)(j + 1) * Hz + kt * 256);
            const float4* w2 = (const float4*)(Wp + (size_t)(j + 2) * Hz + kt * 256);
            const float4* w3 = (const float4*)(Wp + (size_t)(j + 3) * Hz + kt * 256);
            float a0 = acc[c * 4 + 0], a1 = acc[c * 4 + 1];
            float a2 = acc[c * 4 + 2], a3 = acc[c * 4 + 3];
            #pragma unroll 8
            for (int i4 = 0; i4 < 64; ++i4) {
                float h0v = xs[(i4 * 4 + 0) * 33 + lane];
                float h1v = xs[(i4 * 4 + 1) * 33 + lane];
                float h2v = xs[(i4 * 4 + 2) * 33 + lane];
                float h3v = xs[(i4 * 4 + 3) * 33 + lane];
                float4 q0 = w0[i4], q1 = w1[i4], q2 = w2[i4], q3 = w3[i4];
                a0 = fmaf(q0.x, h0v, a0); a0 = fmaf(q0.y, h1v, a0); a0 = fmaf(q0.z, h2v, a0); a0 = fmaf(q0.w, h3v, a0);
                a1 = fmaf(q1.x, h0v, a1); a1 = fmaf(q1.y, h1v, a1); a1 = fmaf(q1.z, h2v, a1); a1 = fmaf(q1.w, h3v, a1);
                a2 = fmaf(q2.x, h0v, a2); a2 = fmaf(q2.y, h1v, a2); a2 = fmaf(q2.z, h2v, a2); a2 = fmaf(q2.w, h3v, a2);
                a3 = fmaf(q3.x, h0v, a3); a3 = fmaf(q3.y, h1v, a3); a3 = fmaf(q3.z, h2v, a3); a3 = fmaf(q3.w, h3v, a3);
            }
            acc[c * 4 + 0] = a0; acc[c * 4 + 1] = a1;
            acc[c * 4 + 2] = a2; acc[c * 4 + 3] = a3;
        }
    }
    #pragma unroll
    for (int c = 0; c < 12; ++c) {
        int rr = rb * 384 + w * 48 + c * 4;
        int g = rr >> 10, j = rr & 1023;
        size_t base = (((size_t)g * Sz + s) * Hz + j) * Bz + lane;
        g_gates[base +  0] = acc[c * 4 + 0];
        g_gates[base + 32] = acc[c * 4 + 1];
        g_gates[base + 64] = acc[c * 4 + 2];
        g_gates[base + 96] = acc[c * 4 + 3];
    }
}

// ---------------------------------------------------------------------------
// scan v2: weights CTA-stationary in SMEM, 4 FMA per LDS'd h element,
// K split across warps with smem partial reduction. 128 CTAs x 256 thr.
//
// SMEM (dynamic floats):
//   ws  [3][8][1024]  = 24576   weights for this CTA's 8 j-columns
//   ht  [256][33]     =  8448   h (or u) k-tile, [k][b] padded
//   part[8*4][32]     =  1024   per-warp partials
// ---------------------------------------------------------------------------
#define SCAN_SMEM_FLOATS (24576 + 8448 + 1024)

__global__ void __launch_bounds__(TPB) scan_kernel(
    const float* __restrict__ Whz, const float* __restrict__ Whr, const float* __restrict__ Whg,
    const float* __restrict__ bz,  const float* __restrict__ br,  const float* __restrict__ bg,
    float* __restrict__ hid_out, int layer)
{
    extern __shared__ float smem[];
    float* ws   = smem;            // 24576
    float* ht   = smem + 24576;    // 8448
    float* part = ht + 8448;       // 1024

    const int tid = threadIdx.x, lane = tid & 31, w = tid >> 5;
    const int jbase = blockIdx.x * 8;
    const int ncta = (int)gridDim.x;

    // ---- preload this CTA's weights (once per layer) ----------------------
    for (int idx = tid; idx < 6144; idx += TPB) {      // 6144 float4
        int g  = idx >> 11;          // 0..2
        int r2 = idx & 2047;
        int jl = r2 >> 8;            // 0..7
        int k4 = r2 & 255;           // 0..255
        const float* W = (g == 0) ? Whz : ((g == 1) ? Whr : Whg);
        float4 v = *(const float4*)(W + (size_t)(jbase + jl) * Hz + k4 * 4);
        *(float4*)&ws[((g * 8 + jl) << 10) + k4 * 4] = v;
    }
    __syncthreads();

    // per-thread reduction identity: (j, b)
    const int jr = tid >> 5;               // local j 0..7
    const int jg = jbase + jr;             // global j
    const int bb = lane;
    const float bzj = bz[jg], brj = br[jg], bgj = bg[jg];
    const size_t plane = (size_t)Sz * Hz * Bz;

    // phase-1 compute mapping: warp = (j-pair, k-half)
    const int jp = w & 3, khalf = w >> 2;
    const int jl0 = 2 * jp, jl1 = 2 * jp + 1;
    // phase-2 compute mapping: warp = (j-quad, k-quarter)
    const int jq = w & 1, kq = w >> 1;

    for (int t = 0; t < Sz; ++t) {
        // ================= phase 1: z, r, u = r*h =========================
        float az0 = 0.f, ar0 = 0.f, az1 = 0.f, ar1 = 0.f;
        for (int p = 0; p < 4; ++p) {
            __syncthreads();
            #pragma unroll
            for (int rep = 0; rep < 8; ++rep) {        // 2048 float4 fill
                int e = rep * 256 + tid;
                int k = e >> 3, bq = e & 7;
                float4 v = *(const float4*)&g_h[(p * 256 + k) * 32 + bq * 4];
                float* d = &ht[k * 33 + bq * 4];
                d[0] = v.x; d[1] = v.y; d[2] = v.z; d[3] = v.w;
            }
            __syncthreads();
            const int kb = khalf * 128;
            const int kgb = p * 256 + kb;
            const float4* wz0 = (const float4*)&ws[(0 * 8 + jl0) * 1024 + kgb];
            const float4* wr0 = (const float4*)&ws[(1 * 8 + jl0) * 1024 + kgb];
            const float4* wz1 = (const float4*)&ws[(0 * 8 + jl1) * 1024 + kgb];
            const float4* wr1 = (const float4*)&ws[(1 * 8 + jl1) * 1024 + kgb];
            const float* hb = &ht[kb * 33 + lane];
            #pragma unroll 8
            for (int i4 = 0; i4 < 32; ++i4) {
                float h0 = hb[(i4 * 4 + 0) * 33];
                float h1 = hb[(i4 * 4 + 1) * 33];
                float h2 = hb[(i4 * 4 + 2) * 33];
                float h3 = hb[(i4 * 4 + 3) * 33];
                float4 qz0 = wz0[i4], qr0 = wr0[i4], qz1 = wz1[i4], qr1 = wr1[i4];
                az0 = fmaf(qz0.x, h0, az0); az0 = fmaf(qz0.y, h1, az0); az0 = fmaf(qz0.z, h2, az0); az0 = fmaf(qz0.w, h3, az0);
                ar0 = fmaf(qr0.x, h0, ar0); ar0 = fmaf(qr0.y, h1, ar0); ar0 = fmaf(qr0.z, h2, ar0); ar0 = fmaf(qr0.w, h3, ar0);
                az1 = fmaf(qz1.x, h0, az1); az1 = fmaf(qz1.y, h1, az1); az1 = fmaf(qz1.z, h2, az1); az1 = fmaf(qz1.w, h3, az1);
                ar1 = fmaf(qr1.x, h0, ar1); ar1 = fmaf(qr1.y, h1, ar1); ar1 = fmaf(qr1.z, h2, ar1); ar1 = fmaf(qr1.w, h3, ar1);
            }
        }
        __syncthreads();                  // protect part[] from previous use
        part[(w * 4 + 0) * 32 + lane] = az0;
        part[(w * 4 + 1) * 32 + lane] = ar0;
        part[(w * 4 + 2) * 32 + lane] = az1;
        part[(w * 4 + 3) * 32 + lane] = ar1;
        __syncthreads();

        // reduce + gates (thread owns (jr, bb))
        const int jp2 = jr >> 1, js = jr & 1;
        float zsum = part[(jp2 * 4 + js * 2 + 0) * 32 + bb]
                   + part[((jp2 + 4) * 4 + js * 2 + 0) * 32 + bb];
        float rsum = part[(jp2 * 4 + js * 2 + 1) * 32 + bb]
                   + part[((jp2 + 4) * 4 + js * 2 + 1) * 32 + bb];
        const size_t gb = ((size_t)t * Hz + jg) * Bz + bb;
        float zg = sigmoidf_(zsum + g_gates[gb] + bzj);
        float rg = sigmoidf_(rsum + g_gates[plane + gb] + brj);
        float hv = g_h[jg * 32 + bb];
        g_u[jg * 32 + bb] = rg * hv;

        grid_bar(2 * t, ncta);

        // ================= phase 2: g, h_new ==============================
        float ag0 = 0.f, ag1 = 0.f, ag2 = 0.f, ag3 = 0.f;
        for (int p = 0; p < 4; ++p) {
            __syncthreads();
            #pragma unroll
            for (int rep = 0; rep < 8; ++rep) {
                int e = rep * 256 + tid;
                int k = e >> 3, bq = e & 7;
                float4 v = *(const float4*)&g_u[(p * 256 + k) * 32 + bq * 4];
                float* d = &ht[k * 33 + bq * 4];
                d[0] = v.x; d[1] = v.y; d[2] = v.z; d[3] = v.w;
            }
            __syncthreads();
            if (p == kq) {
                const int kgb = p * 256;
                const float4* wg0 = (const float4*)&ws[(16 + 4 * jq + 0) * 1024 + kgb];
                const float4* wg1 = (const float4*)&ws[(16 + 4 * jq + 1) * 1024 + kgb];
                const float4* wg2 = (const float4*)&ws[(16 + 4 * jq + 2) * 1024 + kgb];
                const float4* wg3 = (const float4*)&ws[(16 + 4 * jq + 3) * 1024 + kgb];
                const float* hb = &ht[lane];
                #pragma unroll 8
                for (int i4 = 0; i4 < 64; ++i4) {
                    float h0 = hb[(i4 * 4 + 0) * 33];
                    float h1 = hb[(i4 * 4 + 1) * 33];
                    float h2 = hb[(i4 * 4 + 2) * 33];
                    float h3 = hb[(i4 * 4 + 3) * 33];
                    float4 q0 = wg0[i4], q1 = wg1[i4], q2 = wg2[i4], q3 = wg3[i4];
                    ag0 = fmaf(q0.x, h0, ag0); ag0 = fmaf(q0.y, h1, ag0); ag0 = fmaf(q0.z, h2, ag0); ag0 = fmaf(q0.w, h3, ag0);
                    ag1 = fmaf(q1.x, h0, ag1); ag1 = fmaf(q1.y, h1, ag1); ag1 = fmaf(q1.z, h2, ag1); ag1 = fmaf(q1.w, h3, ag1);
                    ag2 = fmaf(q2.x, h0, ag2); ag2 = fmaf(q2.y, h1, ag2); ag2 = fmaf(q2.z, h2, ag2); ag2 = fmaf(q2.w, h3, ag2);
                    ag3 = fmaf(q3.x, h0, ag3); ag3 = fmaf(q3.y, h1, ag3); ag3 = fmaf(q3.w, h3, ag3); ag3 = fmaf(q3.z, h2, ag3);
                }
            }
        }
        __syncthreads();
        part[(w * 4 + 0) * 32 + lane] = ag0;
        part[(w * 4 + 1) * 32 + lane] = ag1;
        part[(w * 4 + 2) * 32 + lane] = ag2;
        part[(w * 4 + 3) * 32 + lane] = ag3;
        __syncthreads();

        const int jq2 = jr >> 2, jl3 = jr & 3;
        float gsum = part[((0 + jq2) * 4 + jl3) * 32 + bb]
                   + part[((2 + jq2) * 4 + jl3) * 32 + bb]
                   + part[((4 + jq2) * 4 + jl3) * 32 + bb]
                   + part[((6 + jq2) * 4 + jl3) * 32 + bb];
        float gv = tanhf(gsum + g_gates[2 * plane + gb] + bgj);
        float hn = zg * hv + (1.0f - zg) * gv;
        g_h[jg * 32 + bb] = hn;
        g_seq[gb] = hn;
        if (t == Sz - 1) hid_out[bb * (2 * Hz) + layer * Hz + jg] = hn;

        grid_bar(2 * t + 1, ncta);
    }
}

// ---------------------------------------------------------------------------
// projY: y[b][s][o] = sum_h seq[s][h][b] * Wy[o][h] + by[o]
// ---------------------------------------------------------------------------
__global__ void __launch_bounds__(TPB) projy_kernel(
    const float* __restrict__ Wy, const float* __restrict__ by, float* __restrict__ y)
{
    __shared__ float xs[256 * 33];
    const int s = blockIdx.x;
    const int tid = threadIdx.x, lane = tid & 31, w = tid >> 5;

    float acc[16];
    #pragma unroll
    for (int q = 0; q < 16; ++q) acc[q] = 0.f;

    for (int kt = 0; kt < 4; ++kt) {
        __syncthreads();
        #pragma unroll
        for (int rep = 0; rep < 32; ++rep) {
            int e = rep * 256 + tid;
            int i = e >> 5, b = e & 31;
            xs[i * 33 + b] = g_seq[((size_t)s * Hz + kt * 256 + i) * Bz + b];
        }
        __syncthreads();
        #pragma unroll
        for (int c = 0; c < 4; ++c) {
            int o = w * 16 + c * 4;
            const float4* w0 = (const float4*)(Wy + (size_t)(o + 0) * Hz + kt * 256);
            const float4* w1 = (const float4*)(Wy + (size_t)(o + 1) * Hz + kt * 256);
            const float4* w2 = (const float4*)(Wy + (size_t)(o + 2) * Hz + kt * 256);
            const float4* w3 = (const float4*)(Wy + (size_t)(o + 3) * Hz + kt * 256);
            float a0 = acc[c * 4 + 0], a1 = acc[c * 4 + 1];
            float a2 = acc[c * 4 + 2], a3 = acc[c * 4 + 3];
            #pragma unroll 8
            for (int i4 = 0; i4 < 64; ++i4) {
                float h0v = xs[(i4 * 4 + 0) * 33 + lane];
                float h1v = xs[(i4 * 4 + 1) * 33 + lane];
                float h2v = xs[(i4 * 4 + 2) * 33 + lane];
                float h3v = xs[(i4 * 4 + 3) * 33 + lane];
                float4 q0 = w0[i4], q1 = w1[i4], q2 = w2[i4], q3 = w3[i4];
                a0 = fmaf(q0.x, h0v, a0); a0 = fmaf(q0.y, h1v, a0); a0 = fmaf(q0.z, h2v, a0); a0 = fmaf(q0.w, h3v, a0);
                a1 = fmaf(q1.x, h0v, a1); a1 = fmaf(q1.y, h1v, a1); a1 = fmaf(q1.z, h2v, a1); a1 = fmaf(q1.w, h3v, a1);
                a2 = fmaf(q2.x, h0v, a2); a2 = fmaf(q2.y, h1v, a2); a2 = fmaf(q2.z, h2v, a2); a2 = fmaf(q2.w, h3v, a2);
                a3 = fmaf(q3.x, h0v, a3); a3 = fmaf(q3.y, h1v, a3); a3 = fmaf(q3.z, h2v, a3); a3 = fmaf(q3.w, h3v, a3);
            }
            acc[c * 4 + 0] = a0; acc[c * 4 + 1] = a1;
            acc[c * 4 + 2] = a2; acc[c * 4 + 3] = a3;
        }
    }
    #pragma unroll
    for (int c = 0; c < 4; ++c) {
        #pragma unroll
        for (int q = 0; q < 4; ++q) {
            int o = w * 16 + c * 4 + q;
            y[(size_t)lane * (Sz * Oz) + (size_t)s * Oz + o] = acc[c * 4 + q] + by[o];
        }
    }
}

// ---------------------------------------------------------------------------
extern "C" void kernel_launch(void* const* d_in, const int* in_sizes, int n_in,
                              void* d_out, int out_size) {
    (void)in_sizes; (void)n_in; (void)out_size;
    const float* x    = (const float*)d_in[0];
    const float* h0   = (const float*)d_in[1];
    const float* Wxz0 = (const float*)d_in[2];
    const float* Whz0 = (const float*)d_in[3];
    const float* bz0  = (const float*)d_in[4];
    const float* Wxr0 = (const float*)d_in[5];
    const float* Whr0 = (const float*)d_in[6];
    const float* br0  = (const float*)d_in[7];
    const float* Wxg0 = (const float*)d_in[8];
    const float* Whg0 = (const float*)d_in[9];
    const float* bg0  = (const float*)d_in[10];
    const float* Wxz1 = (const float*)d_in[11];
    const float* Whz1 = (const float*)d_in[12];
    const float* bz1  = (const float*)d_in[13];
    const float* Wxr1 = (const float*)d_in[14];
    const float* Whr1 = (const float*)d_in[15];
    const float* br1  = (const float*)d_in[16];
    const float* Wxg1 = (const float*)d_in[17];
    const float* Whg1 = (const float*)d_in[18];
    const float* bg1  = (const float*)d_in[19];
    const float* Wy   = (const float*)d_in[20];
    const float* by   = (const float*)d_in[21];

    float* y   = (float*)d_out;
    float* hid = (float*)d_out + (size_t)Bz * Sz * Oz;

    const int scan_smem = SCAN_SMEM_FLOATS * (int)sizeof(float);
    cudaFuncSetAttribute(scan_kernel, cudaFuncAttributeMaxDynamicSharedMemorySize, scan_smem);

    // Layer 0
    proj0_kernel<<<Sz, TPB>>>(x, Wxz0, Wxr0, Wxg0);
    prep_kernel<<<SCAN_GRID, TPB>>>(h0, 0);
    scan_kernel<<<SCAN_GRID, TPB, scan_smem>>>(Whz0, Whr0, Whg0, bz0, br0, bg0, hid, 0);

    // Layer 1
    proj1_kernel<<<dim3(8, Sz), TPB>>>(Wxz1, Wxr1, Wxg1);
    prep_kernel<<<SCAN_GRID, TPB>>>(h0, 1);
    scan_kernel<<<SCAN_GRID, TPB, scan_smem>>>(Whz1, Whr1, Whg1, bz1, br1, bg1, hid, 1);

    // Output head
    projy_kernel<<<Sz, TPB>>>(Wy, by, y);
}